// round 14
// baseline (speedup 1.0000x reference)
#include <cuda_runtime.h>
#include <cuda_fp16.h>
#include <cstdint>

#define NB 4
#define NT 2048
#define NDIM 1024
#define NH 16
#define NDH 64
#define BHN (NB*NH)

// softmax scale folded into Q: 0.125 * log2(e)
#define C2F 0.18033688011112042f
// fp16x2 {1.0, 1.0}
#define ONES_H2 0x3C003C00u

// ---------------- scratch ----------------
__device__ __half g_xh[NB*NT*NDIM];
__device__ __half g_Wqkv[NDIM*3*NDIM];   // [k=1024][n=3072], permuted cols
__device__ __half g_Wo[NDIM*NDIM];       // [k=1024][n=1024]
__device__ __half g_Q[BHN*NT*NDH];       // pre-scaled by C2F
__device__ __half g_K[BHN*NT*NDH];
__device__ __half g_V[BHN*NT*NDH];
__device__ __half g_O[NB*NT*NDIM];

// ---------------- helpers ----------------
__device__ __forceinline__ unsigned smem_u32(const void* p) {
    return (unsigned)__cvta_generic_to_shared(p);
}
__device__ __forceinline__ void cp16(void* s, const void* g) {
    asm volatile("cp.async.cg.shared.global [%0], [%1], 16;\n"
                 :: "r"(smem_u32(s)), "l"(g));
}
__device__ __forceinline__ void cp_commit() { asm volatile("cp.async.commit_group;\n"); }
template <int N>
__device__ __forceinline__ void cp_wait() { asm volatile("cp.async.wait_group %0;\n" :: "n"(N)); }

__device__ __forceinline__ void ldsm_x4(unsigned r[4], const void* p) {
    unsigned a = smem_u32(p);
    asm volatile("ldmatrix.sync.aligned.m8n8.x4.shared.b16 {%0,%1,%2,%3}, [%4];\n"
                 : "=r"(r[0]), "=r"(r[1]), "=r"(r[2]), "=r"(r[3]) : "r"(a));
}
__device__ __forceinline__ void ldsm_x4t(unsigned r[4], const void* p) {
    unsigned a = smem_u32(p);
    asm volatile("ldmatrix.sync.aligned.m8n8.x4.trans.shared.b16 {%0,%1,%2,%3}, [%4];\n"
                 : "=r"(r[0]), "=r"(r[1]), "=r"(r[2]), "=r"(r[3]) : "r"(a));
}
__device__ __forceinline__ void mma_16816(float c[4], const unsigned a[4], const unsigned b[2]) {
    asm volatile(
        "mma.sync.aligned.m16n8k16.row.col.f32.f16.f16.f32 "
        "{%0,%1,%2,%3}, {%4,%5,%6,%7}, {%8,%9}, {%0,%1,%2,%3};\n"
        : "+f"(c[0]), "+f"(c[1]), "+f"(c[2]), "+f"(c[3])
        : "r"(a[0]), "r"(a[1]), "r"(a[2]), "r"(a[3]), "r"(b[0]), "r"(b[1]));
}
// init form: D = A*B + 0
__device__ __forceinline__ void mma_16816_z(float d[4], const unsigned a[4], const unsigned b[2]) {
    asm volatile(
        "mma.sync.aligned.m16n8k16.row.col.f32.f16.f16.f32 "
        "{%0,%1,%2,%3}, {%4,%5,%6,%7}, {%8,%9}, {%10,%11,%12,%13};\n"
        : "=f"(d[0]), "=f"(d[1]), "=f"(d[2]), "=f"(d[3])
        : "r"(a[0]), "r"(a[1]), "r"(a[2]), "r"(a[3]), "r"(b[0]), "r"(b[1]),
          "f"(0.f), "f"(0.f), "f"(0.f), "f"(0.f));
}
__device__ __forceinline__ unsigned packh2(float lo, float hi) {
    __half2 h = __floats2half2_rn(lo, hi);
    return *reinterpret_cast<unsigned*>(&h);
}
__device__ __forceinline__ unsigned h2ex2(unsigned x) {
    unsigned y;
    asm("ex2.approx.f16x2 %0, %1;" : "=r"(y) : "r"(x));
    return y;
}

// ---------------- fused conversion kernel ----------------
#define NX4 ((NB*NT*NDIM)/4)
#define NPW (NDIM*3*NDIM)
#define NW4 ((NDIM*NDIM)/4)
__global__ void cvt_all_kernel(const float* __restrict__ x,
                               const float* __restrict__ Wqkv,
                               const float* __restrict__ Wo) {
    int i = blockIdx.x * blockDim.x + threadIdx.x;
    int total = NX4 + NPW + NW4;
    for (; i < total; i += gridDim.x * blockDim.x) {
        if (i < NX4) {
            float4 v = reinterpret_cast<const float4*>(x)[i];
            __half2* dst = reinterpret_cast<__half2*>(g_xh) + i*2;
            dst[0] = __floats2half2_rn(v.x, v.y);
            dst[1] = __floats2half2_rn(v.z, v.w);
        } else if (i < NX4 + NPW) {
            int j = i - NX4;
            int k   = j / (3*NDIM);
            int nn  = j - k * (3*NDIM);
            int kqv = nn >> 10;
            int rem = nn & 1023;
            int h   = rem >> 6;
            int d   = rem & 63;
            g_Wqkv[j] = __float2half_rn(Wqkv[k*(3*NDIM) + d*48 + kqv*16 + h]);
        } else {
            int j = i - NX4 - NPW;
            float4 v = reinterpret_cast<const float4*>(Wo)[j];
            __half2* dst = reinterpret_cast<__half2*>(g_Wo) + j*2;
            dst[0] = __floats2half2_rn(v.x, v.y);
            dst[1] = __floats2half2_rn(v.z, v.w);
        }
    }
}

// ---------------- pipelined GEMM (R12 proven: 8 warps, 64x32 warp tile) ----------------
#define GEMM_SMEM_BYTES ((2*128*72 + 2*64*136) * 2)

template <int MODE>
__global__ __launch_bounds__(256, 2) void gemm_kernel(
    const __half* __restrict__ A, const __half* __restrict__ Bm,
    int K, int ldb, float* __restrict__ outF)
{
    extern __shared__ __half dyn[];
    __half* As0 = dyn;                 // [2][128][72]
    __half* Bs0 = dyn + 2*128*72;      // [2][64][136]
#define AS(bf,r,c) As0[((bf)*128 + (r))*72 + (c)]
#define BS(bf,r,c) Bs0[((bf)*64  + (r))*136 + (c)]

    const int tid  = threadIdx.x;
    const int lane = tid & 31;
    const int warp = tid >> 5;
    const int wm   = warp & 1;
    const int wn   = warp >> 1;
    const int m0   = blockIdx.y * 128;
    const int n0   = blockIdx.x * 128;

    const int ar[4] = { (tid+0)>>3, (tid+256)>>3, (tid+512)>>3, (tid+768)>>3 };
    const int ac    = (tid & 7) * 8;
    const int br[4] = { (tid+0)>>4, (tid+256)>>4, (tid+512)>>4, (tid+768)>>4 };
    const int bc    = (tid & 15) * 8;

    float acc[4][4][4];
#pragma unroll
    for (int mt = 0; mt < 4; mt++)
#pragma unroll
        for (int nt = 0; nt < 4; nt++)
#pragma unroll
            for (int e = 0; e < 4; e++) acc[mt][nt][e] = 0.f;

    const int ntiles = K >> 6;

#define G_FILL(bf, kb) do {                                                    \
        _Pragma("unroll")                                                      \
        for (int i_ = 0; i_ < 4; i_++)                                         \
            cp16(&AS(bf, ar[i_], ac), &A[(size_t)(m0 + ar[i_])*K + (kb) + ac]);\
        _Pragma("unroll")                                                      \
        for (int i_ = 0; i_ < 4; i_++)                                         \
            cp16(&BS(bf, br[i_], bc), &Bm[(size_t)((kb) + br[i_])*ldb + n0 + bc]); \
        cp_commit();                                                           \
    } while (0)

    G_FILL(0, 0);

    for (int it = 0; it < ntiles; it++) {
        const int buf = it & 1;
        cp_wait<0>();
        __syncthreads();
        if (it + 1 < ntiles) G_FILL(buf^1, (it + 1) << 6);

#pragma unroll
        for (int kk = 0; kk < 4; kk++) {
            unsigned af[4][4], bfr[4][2];
#pragma unroll
            for (int mt = 0; mt < 4; mt++)
                ldsm_x4(af[mt], &AS(buf, wm*64 + mt*16 + (lane & 15), kk*16 + (lane >> 4)*8));
#pragma unroll
            for (int nt2 = 0; nt2 < 2; nt2++) {
                unsigned bq[4];
                ldsm_x4t(bq, &BS(buf, kk*16 + (lane & 15), wn*32 + nt2*16 + (lane >> 4)*8));
                bfr[2*nt2  ][0] = bq[0]; bfr[2*nt2  ][1] = bq[1];
                bfr[2*nt2+1][0] = bq[2]; bfr[2*nt2+1][1] = bq[3];
            }
#pragma unroll
            for (int mt = 0; mt < 4; mt++)
#pragma unroll
                for (int nt = 0; nt < 4; nt++)
                    mma_16816(acc[mt][nt], af[mt], bfr[nt]);
        }
    }

    // epilogue: per-nt hoisted pointers
#pragma unroll
    for (int nt = 0; nt < 4; nt++) {
        const int col = n0 + wn*32 + nt*8 + (lane & 3)*2;
        if (MODE == 0) {
            const int kqv = col >> 10;
            const int rem = col & 1023;
            const int h   = rem >> 6;
            const int d   = rem & 63;
            const float sc = (kqv == 0) ? C2F : 1.0f;
            __half* base = (kqv == 0) ? g_Q : ((kqv == 1) ? g_K : g_V);
#pragma unroll
            for (int mt = 0; mt < 4; mt++) {
                int row = m0 + wm*64 + mt*16 + (lane >> 2);
                int b0  = row >> 11, t0 = row & 2047;
                *reinterpret_cast<__half2*>(
                    &base[(((size_t)(b0*NH + h))*NT + t0)*NDH + d]) =
                    __floats2half2_rn(acc[mt][nt][0]*sc, acc[mt][nt][1]*sc);
                int row1 = row + 8;
                int b1 = row1 >> 11, t1 = row1 & 2047;
                *reinterpret_cast<__half2*>(
                    &base[(((size_t)(b1*NH + h))*NT + t1)*NDH + d]) =
                    __floats2half2_rn(acc[mt][nt][2]*sc, acc[mt][nt][3]*sc);
            }
        } else {
#pragma unroll
            for (int mt = 0; mt < 4; mt++) {
                int row = m0 + wm*64 + mt*16 + (lane >> 2);
                *reinterpret_cast<float2*>(&outF[(size_t)row*NDIM + col]) =
                    make_float2(acc[mt][nt][0], acc[mt][nt][1]);
                *reinterpret_cast<float2*>(&outF[(size_t)(row+8)*NDIM + col]) =
                    make_float2(acc[mt][nt][2], acc[mt][nt][3]);
            }
        }
    }
#undef AS
#undef BS
#undef G_FILL
}

// ---------------- flash attention (R12 config + forced 4-CTA occupancy) ----------------
#define ATTN_SMEM_BYTES ((128*72 + 2*64*72 + 2*64*72) * 2)

__global__ __launch_bounds__(128, 4) void attn_kernel() {
    extern __shared__ __half dynA[];
    __half* Qs0 = dynA;
    __half* Ks0 = dynA + 128*72;
    __half* Vs0 = dynA + 128*72 + 2*64*72;
#define QS(r,c)    Qs0[(r)*72 + (c)]
#define KS(bf,r,c) Ks0[((bf)*64 + (r))*72 + (c)]
#define VS(bf,r,c) Vs0[((bf)*64 + (r))*72 + (c)]

    const int tid  = threadIdx.x;
    const int lane = tid & 31;
    const int warp = tid >> 5;
    const int qb   = blockIdx.x * 128;
    const int bh   = blockIdx.y;

    const __half* Qp = g_Q + (size_t)bh * NT * NDH;
    const __half* Kp = g_K + (size_t)bh * NT * NDH;
    const __half* Vp = g_V + (size_t)bh * NT * NDH;

    const int kr[4] = { (tid+0)>>3, (tid+128)>>3, (tid+256)>>3, (tid+384)>>3 };
    const int kc    = (tid & 7) * 8;

#define A_FILL(bf, jb) do {                                                    \
        _Pragma("unroll")                                                      \
        for (int i_ = 0; i_ < 4; i_++) {                                       \
            cp16(&KS(bf, kr[i_], kc), &Kp[(size_t)((jb) + kr[i_])*NDH + kc]);  \
            cp16(&VS(bf, kr[i_], kc), &Vp[(size_t)((jb) + kr[i_])*NDH + kc]);  \
        }                                                                      \
        cp_commit();                                                           \
    } while (0)

    // prologue: Q + KV tile 0
#pragma unroll
    for (int i = 0; i < 8; i++) {
        int id = tid + 128*i;
        int r  = id >> 3;
        cp16(&QS(r, kc), &Qp[(size_t)(qb + r)*NDH + kc]);
    }
    A_FILL(0, 0);
    cp_wait<0>();
    __syncthreads();

    unsigned qf[2][4][4];
#pragma unroll
    for (int mt = 0; mt < 2; mt++)
#pragma unroll
        for (int kt = 0; kt < 4; kt++)
            ldsm_x4(qf[mt][kt], &QS(warp*32 + mt*16 + (lane & 15), kt*16 + (lane >> 4)*8));

    float o[2][9][4];
#pragma unroll
    for (int mt = 0; mt < 2; mt++)
#pragma unroll
        for (int nt = 0; nt < 9; nt++)
#pragma unroll
            for (int e = 0; e < 4; e++) o[mt][nt][e] = 0.f;

    const unsigned ones_frag[2] = { ONES_H2, ONES_H2 };

    const int ntiles = NT >> 6;

    for (int it = 0; it < ntiles; it++) {
        const int buf = it & 1;
        if (it + 1 < ntiles) A_FILL(buf^1, (it + 1) << 6);

        // S = Q K^T   (kt=0 init-form MMA)
        float sv[2][8][4];
        {
            unsigned kf[8][2];
#pragma unroll
            for (int nt2 = 0; nt2 < 4; nt2++) {
                unsigned kq[4];
                ldsm_x4(kq, &KS(buf, nt2*16 + (lane >> 4)*8 + (lane & 7),
                                     ((lane >> 3) & 1)*8));
                kf[2*nt2  ][0] = kq[0]; kf[2*nt2  ][1] = kq[1];
                kf[2*nt2+1][0] = kq[2]; kf[2*nt2+1][1] = kq[3];
            }
#pragma unroll
            for (int mt = 0; mt < 2; mt++)
#pragma unroll
                for (int nt = 0; nt < 8; nt++)
                    mma_16816_z(sv[mt][nt], qf[mt][0], kf[nt]);
        }
#pragma unroll
        for (int kt = 1; kt < 4; kt++) {
            unsigned kf[8][2];
#pragma unroll
            for (int nt2 = 0; nt2 < 4; nt2++) {
                unsigned kq[4];
                ldsm_x4(kq, &KS(buf, nt2*16 + (lane >> 4)*8 + (lane & 7),
                                     kt*16 + ((lane >> 3) & 1)*8));
                kf[2*nt2  ][0] = kq[0]; kf[2*nt2  ][1] = kq[1];
                kf[2*nt2+1][0] = kq[2]; kf[2*nt2+1][1] = kq[3];
            }
#pragma unroll
            for (int mt = 0; mt < 2; mt++)
#pragma unroll
                for (int nt = 0; nt < 8; nt++)
                    mma_16816(sv[mt][nt], qf[mt][kt], kf[nt]);
        }

        // p = 2^s (f16x2) -> PV A-fragment
        unsigned pf[2][4][4];
#pragma unroll
        for (int mt = 0; mt < 2; mt++)
#pragma unroll
            for (int kt = 0; kt < 4; kt++) {
                pf[mt][kt][0] = h2ex2(packh2(sv[mt][2*kt  ][0], sv[mt][2*kt  ][1]));
                pf[mt][kt][1] = h2ex2(packh2(sv[mt][2*kt  ][2], sv[mt][2*kt  ][3]));
                pf[mt][kt][2] = h2ex2(packh2(sv[mt][2*kt+1][0], sv[mt][2*kt+1][1]));
                pf[mt][kt][3] = h2ex2(packh2(sv[mt][2*kt+1][2], sv[mt][2*kt+1][3]));
            }

        // O += P V  (nt=8 uses the constant ones fragment -> denominator)
#pragma unroll
        for (int kt = 0; kt < 4; kt++) {
            unsigned vf[8][2];
#pragma unroll
            for (int nt2 = 0; nt2 < 4; nt2++) {
                unsigned vq[4];
                ldsm_x4t(vq, &VS(buf, kt*16 + (lane & 15), nt2*16 + (lane >> 4)*8));
                vf[2*nt2  ][0] = vq[0]; vf[2*nt2  ][1] = vq[1];
                vf[2*nt2+1][0] = vq[2]; vf[2*nt2+1][1] = vq[3];
            }
#pragma unroll
            for (int mt = 0; mt < 2; mt++) {
#pragma unroll
                for (int nt = 0; nt < 8; nt++)
                    mma_16816(o[mt][nt], pf[mt][kt], vf[nt]);
                mma_16816(o[mt][8], pf[mt][kt], ones_frag);
            }
        }

        if (it + 1 < ntiles) {
            cp_wait<0>();
            __syncthreads();
        }
    }

    const int b = bh >> 4;
    const int h = bh & 15;
#pragma unroll
    for (int mt = 0; mt < 2; mt++) {
#pragma unroll
        for (int hr = 0; hr < 2; hr++) {
            float inv = 1.0f / o[mt][8][hr*2];
            int row = qb + warp*32 + mt*16 + (lane >> 2) + hr*8;
            size_t rowoff = ((size_t)b*NT + row)*NDIM + h*NDH;
#pragma unroll
            for (int nt = 0; nt < 8; nt++) {
                int col = nt*8 + (lane & 3)*2;
                *reinterpret_cast<__half2*>(&g_O[rowoff + col]) =
                    __floats2half2_rn(o[mt][nt][hr*2+0]*inv, o[mt][nt][hr*2+1]*inv);
            }
        }
    }
#undef QS
#undef KS
#undef VS
#undef A_FILL
}

// ---------------- launch ----------------
extern "C" void kernel_launch(void* const* d_in, const int* in_sizes, int n_in,
                              void* d_out, int out_size) {
    (void)in_sizes; (void)n_in; (void)out_size;
    const float* x    = (const float*)d_in[0];
    const float* Wqkv = (const float*)d_in[1];
    const float* Wo   = (const float*)d_in[2];
    float* out = (float*)d_out;

    static bool attr_done = false;
    if (!attr_done) {
        cudaFuncSetAttribute(gemm_kernel<0>, cudaFuncAttributeMaxDynamicSharedMemorySize, GEMM_SMEM_BYTES);
        cudaFuncSetAttribute(gemm_kernel<1>, cudaFuncAttributeMaxDynamicSharedMemorySize, GEMM_SMEM_BYTES);
        cudaFuncSetAttribute(attn_kernel,    cudaFuncAttributeMaxDynamicSharedMemorySize, ATTN_SMEM_BYTES);
        attr_done = true;
    }

    __half *xh_p, *wqkv_p, *wo_p, *o_p;
    cudaGetSymbolAddress((void**)&xh_p,   g_xh);
    cudaGetSymbolAddress((void**)&wqkv_p, g_Wqkv);
    cudaGetSymbolAddress((void**)&wo_p,   g_Wo);
    cudaGetSymbolAddress((void**)&o_p,    g_O);

    cvt_all_kernel<<<4096, 256>>>(x, Wqkv, Wo);

    {
        dim3 grid(3*NDIM/128, NB*NT/128);   // (24, 64)
        gemm_kernel<0><<<grid, 256, GEMM_SMEM_BYTES>>>(xh_p, wqkv_p, NDIM, 3*NDIM, nullptr);
    }
    {
        dim3 grid(NT/128, BHN);             // (16, 64)
        attn_kernel<<<grid, 128, ATTN_SMEM_BYTES>>>();
    }
    {
        dim3 grid(NDIM/128, NB*NT/128);     // (8, 64)
        gemm_kernel<1><<<grid, 256, GEMM_SMEM_BYTES>>>(o_p, wo_p, NDIM, NDIM, out);
    }
}

// round 15
// speedup vs baseline: 1.0411x; 1.0411x over previous
#include <cuda_runtime.h>
#include <cuda_fp16.h>
#include <cstdint>

#define NB 4
#define NT 2048
#define NDIM 1024
#define NH 16
#define NDH 64
#define BHN (NB*NH)

// softmax scale folded into Q: 0.125 * log2(e)
#define C2F 0.18033688011112042f
// fp16x2 {1.0, 1.0}
#define ONES_H2 0x3C003C00u

// ---------------- scratch ----------------
__device__ __half g_xh[NB*NT*NDIM];
__device__ __half g_Wqkv[NDIM*3*NDIM];   // [k=1024][n=3072], permuted cols
__device__ __half g_Wo[NDIM*NDIM];       // [k=1024][n=1024]
__device__ __half g_Q[BHN*NT*NDH];       // pre-scaled by C2F
__device__ __half g_K[BHN*NT*NDH];
__device__ __half g_V[BHN*NT*NDH];
__device__ __half g_O[NB*NT*NDIM];

// ---------------- helpers ----------------
__device__ __forceinline__ unsigned smem_u32(const void* p) {
    return (unsigned)__cvta_generic_to_shared(p);
}
__device__ __forceinline__ void cp16(void* s, const void* g) {
    asm volatile("cp.async.cg.shared.global [%0], [%1], 16;\n"
                 :: "r"(smem_u32(s)), "l"(g));
}
__device__ __forceinline__ void cp_commit() { asm volatile("cp.async.commit_group;\n"); }
template <int N>
__device__ __forceinline__ void cp_wait() { asm volatile("cp.async.wait_group %0;\n" :: "n"(N)); }

__device__ __forceinline__ void ldsm_x4(unsigned r[4], const void* p) {
    unsigned a = smem_u32(p);
    asm volatile("ldmatrix.sync.aligned.m8n8.x4.shared.b16 {%0,%1,%2,%3}, [%4];\n"
                 : "=r"(r[0]), "=r"(r[1]), "=r"(r[2]), "=r"(r[3]) : "r"(a));
}
__device__ __forceinline__ void ldsm_x4t(unsigned r[4], const void* p) {
    unsigned a = smem_u32(p);
    asm volatile("ldmatrix.sync.aligned.m8n8.x4.trans.shared.b16 {%0,%1,%2,%3}, [%4];\n"
                 : "=r"(r[0]), "=r"(r[1]), "=r"(r[2]), "=r"(r[3]) : "r"(a));
}
__device__ __forceinline__ void mma_16816(float c[4], const unsigned a[4], const unsigned b[2]) {
    asm volatile(
        "mma.sync.aligned.m16n8k16.row.col.f32.f16.f16.f32 "
        "{%0,%1,%2,%3}, {%4,%5,%6,%7}, {%8,%9}, {%0,%1,%2,%3};\n"
        : "+f"(c[0]), "+f"(c[1]), "+f"(c[2]), "+f"(c[3])
        : "r"(a[0]), "r"(a[1]), "r"(a[2]), "r"(a[3]), "r"(b[0]), "r"(b[1]));
}
// init form: D = A*B + 0
__device__ __forceinline__ void mma_16816_z(float d[4], const unsigned a[4], const unsigned b[2]) {
    asm volatile(
        "mma.sync.aligned.m16n8k16.row.col.f32.f16.f16.f32 "
        "{%0,%1,%2,%3}, {%4,%5,%6,%7}, {%8,%9}, {%10,%11,%12,%13};\n"
        : "=f"(d[0]), "=f"(d[1]), "=f"(d[2]), "=f"(d[3])
        : "r"(a[0]), "r"(a[1]), "r"(a[2]), "r"(a[3]), "r"(b[0]), "r"(b[1]),
          "f"(0.f), "f"(0.f), "f"(0.f), "f"(0.f));
}
__device__ __forceinline__ unsigned packh2(float lo, float hi) {
    __half2 h = __floats2half2_rn(lo, hi);
    return *reinterpret_cast<unsigned*>(&h);
}
__device__ __forceinline__ unsigned h2ex2(unsigned x) {
    unsigned y;
    asm("ex2.approx.f16x2 %0, %1;" : "=r"(y) : "r"(x));
    return y;
}

// ---------------- conversion kernels ----------------
// x + Wo: grid-stride vec4 convert
#define NX4 ((NB*NT*NDIM)/4)
#define NW4 ((NDIM*NDIM)/4)
__global__ void cvt_xw_kernel(const float* __restrict__ x,
                              const float* __restrict__ Wo) {
    int i = blockIdx.x * blockDim.x + threadIdx.x;
    int total = NX4 + NW4;
    for (; i < total; i += gridDim.x * blockDim.x) {
        if (i < NX4) {
            float4 v = reinterpret_cast<const float4*>(x)[i];
            __half2* dst = reinterpret_cast<__half2*>(g_xh) + i*2;
            dst[0] = __floats2half2_rn(v.x, v.y);
            dst[1] = __floats2half2_rn(v.z, v.w);
        } else {
            int j = i - NX4;
            float4 v = reinterpret_cast<const float4*>(Wo)[j];
            __half2* dst = reinterpret_cast<__half2*>(g_Wo) + j*2;
            dst[0] = __floats2half2_rn(v.x, v.y);
            dst[1] = __floats2half2_rn(v.z, v.w);
        }
    }
}

// W_qkv permute via smem staging: one CTA per k-row.
// Read row k coalesced (3072 floats), write permuted in n-order (coalesced),
// random access resolved in shared memory.
__global__ __launch_bounds__(256) void permw_kernel(const float* __restrict__ src) {
    __shared__ float row[3*NDIM];
    const int k = blockIdx.x;
    const float* srow = src + (size_t)k * (3*NDIM);
    // coalesced load: 3072 floats / 256 thr = 12 each (float4: 768 / 256 = 3)
#pragma unroll
    for (int i = 0; i < 3; i++) {
        int idx = threadIdx.x + 256*i;
        reinterpret_cast<float4*>(row)[idx] =
            reinterpret_cast<const float4*>(srow)[idx];
    }
    __syncthreads();
    // coalesced store in n_new order: n_new = kqv*1024 + h*64 + d, c = d*48 + kqv*16 + h
    __half* drow = g_Wqkv + (size_t)k * (3*NDIM);
#pragma unroll
    for (int i = 0; i < 12; i++) {
        int n   = threadIdx.x + 256*i;
        int kqv = n >> 10;
        int rem = n & 1023;
        int h   = rem >> 6;
        int d   = rem & 63;
        drow[n] = __float2half_rn(row[d*48 + kqv*16 + h]);
    }
}

// ---------------- pipelined GEMM (R12 proven: 8 warps, 64x32 warp tile) ----------------
#define GEMM_SMEM_BYTES ((2*128*72 + 2*64*136) * 2)

template <int MODE>
__global__ __launch_bounds__(256, 2) void gemm_kernel(
    const __half* __restrict__ A, const __half* __restrict__ Bm,
    int K, int ldb, float* __restrict__ outF)
{
    extern __shared__ __half dyn[];
    __half* As0 = dyn;                 // [2][128][72]
    __half* Bs0 = dyn + 2*128*72;      // [2][64][136]
#define AS(bf,r,c) As0[((bf)*128 + (r))*72 + (c)]
#define BS(bf,r,c) Bs0[((bf)*64  + (r))*136 + (c)]

    const int tid  = threadIdx.x;
    const int lane = tid & 31;
    const int warp = tid >> 5;
    const int wm   = warp & 1;
    const int wn   = warp >> 1;
    const int m0   = blockIdx.y * 128;
    const int n0   = blockIdx.x * 128;

    const int ar[4] = { (tid+0)>>3, (tid+256)>>3, (tid+512)>>3, (tid+768)>>3 };
    const int ac    = (tid & 7) * 8;
    const int br[4] = { (tid+0)>>4, (tid+256)>>4, (tid+512)>>4, (tid+768)>>4 };
    const int bc    = (tid & 15) * 8;

    float acc[4][4][4];
#pragma unroll
    for (int mt = 0; mt < 4; mt++)
#pragma unroll
        for (int nt = 0; nt < 4; nt++)
#pragma unroll
            for (int e = 0; e < 4; e++) acc[mt][nt][e] = 0.f;

    const int ntiles = K >> 6;

#define G_FILL(bf, kb) do {                                                    \
        _Pragma("unroll")                                                      \
        for (int i_ = 0; i_ < 4; i_++)                                         \
            cp16(&AS(bf, ar[i_], ac), &A[(size_t)(m0 + ar[i_])*K + (kb) + ac]);\
        _Pragma("unroll")                                                      \
        for (int i_ = 0; i_ < 4; i_++)                                         \
            cp16(&BS(bf, br[i_], bc), &Bm[(size_t)((kb) + br[i_])*ldb + n0 + bc]); \
        cp_commit();                                                           \
    } while (0)

    G_FILL(0, 0);

    for (int it = 0; it < ntiles; it++) {
        const int buf = it & 1;
        cp_wait<0>();
        __syncthreads();
        if (it + 1 < ntiles) G_FILL(buf^1, (it + 1) << 6);

#pragma unroll
        for (int kk = 0; kk < 4; kk++) {
            unsigned af[4][4], bfr[4][2];
#pragma unroll
            for (int mt = 0; mt < 4; mt++)
                ldsm_x4(af[mt], &AS(buf, wm*64 + mt*16 + (lane & 15), kk*16 + (lane >> 4)*8));
#pragma unroll
            for (int nt2 = 0; nt2 < 2; nt2++) {
                unsigned bq[4];
                ldsm_x4t(bq, &BS(buf, kk*16 + (lane & 15), wn*32 + nt2*16 + (lane >> 4)*8));
                bfr[2*nt2  ][0] = bq[0]; bfr[2*nt2  ][1] = bq[1];
                bfr[2*nt2+1][0] = bq[2]; bfr[2*nt2+1][1] = bq[3];
            }
#pragma unroll
            for (int mt = 0; mt < 4; mt++)
#pragma unroll
                for (int nt = 0; nt < 4; nt++)
                    mma_16816(acc[mt][nt], af[mt], bfr[nt]);
        }
    }

    // epilogue: per-nt hoisted pointers
#pragma unroll
    for (int nt = 0; nt < 4; nt++) {
        const int col = n0 + wn*32 + nt*8 + (lane & 3)*2;
        if (MODE == 0) {
            const int kqv = col >> 10;
            const int rem = col & 1023;
            const int h   = rem >> 6;
            const int d   = rem & 63;
            const float sc = (kqv == 0) ? C2F : 1.0f;
            __half* base = (kqv == 0) ? g_Q : ((kqv == 1) ? g_K : g_V);
#pragma unroll
            for (int mt = 0; mt < 4; mt++) {
                int row = m0 + wm*64 + mt*16 + (lane >> 2);
                int b0  = row >> 11, t0 = row & 2047;
                *reinterpret_cast<__half2*>(
                    &base[(((size_t)(b0*NH + h))*NT + t0)*NDH + d]) =
                    __floats2half2_rn(acc[mt][nt][0]*sc, acc[mt][nt][1]*sc);
                int row1 = row + 8;
                int b1 = row1 >> 11, t1 = row1 & 2047;
                *reinterpret_cast<__half2*>(
                    &base[(((size_t)(b1*NH + h))*NT + t1)*NDH + d]) =
                    __floats2half2_rn(acc[mt][nt][2]*sc, acc[mt][nt][3]*sc);
            }
        } else {
#pragma unroll
            for (int mt = 0; mt < 4; mt++) {
                int row = m0 + wm*64 + mt*16 + (lane >> 2);
                *reinterpret_cast<float2*>(&outF[(size_t)row*NDIM + col]) =
                    make_float2(acc[mt][nt][0], acc[mt][nt][1]);
                *reinterpret_cast<float2*>(&outF[(size_t)(row+8)*NDIM + col]) =
                    make_float2(acc[mt][nt][2], acc[mt][nt][3]);
            }
        }
    }
#undef AS
#undef BS
#undef G_FILL
}

// ---------------- flash attention (R12 proven config, NO launch bound) ----------------
#define ATTN_SMEM_BYTES ((128*72 + 2*64*72 + 2*64*72) * 2)

__global__ __launch_bounds__(128) void attn_kernel() {
    extern __shared__ __half dynA[];
    __half* Qs0 = dynA;
    __half* Ks0 = dynA + 128*72;
    __half* Vs0 = dynA + 128*72 + 2*64*72;
#define QS(r,c)    Qs0[(r)*72 + (c)]
#define KS(bf,r,c) Ks0[((bf)*64 + (r))*72 + (c)]
#define VS(bf,r,c) Vs0[((bf)*64 + (r))*72 + (c)]

    const int tid  = threadIdx.x;
    const int lane = tid & 31;
    const int warp = tid >> 5;
    const int qb   = blockIdx.x * 128;
    const int bh   = blockIdx.y;

    const __half* Qp = g_Q + (size_t)bh * NT * NDH;
    const __half* Kp = g_K + (size_t)bh * NT * NDH;
    const __half* Vp = g_V + (size_t)bh * NT * NDH;

    const int kr[4] = { (tid+0)>>3, (tid+128)>>3, (tid+256)>>3, (tid+384)>>3 };
    const int kc    = (tid & 7) * 8;

#define A_FILL(bf, jb) do {                                                    \
        _Pragma("unroll")                                                      \
        for (int i_ = 0; i_ < 4; i_++) {                                       \
            cp16(&KS(bf, kr[i_], kc), &Kp[(size_t)((jb) + kr[i_])*NDH + kc]);  \
            cp16(&VS(bf, kr[i_], kc), &Vp[(size_t)((jb) + kr[i_])*NDH + kc]);  \
        }                                                                      \
        cp_commit();                                                           \
    } while (0)

    // prologue: Q + KV tile 0
#pragma unroll
    for (int i = 0; i < 8; i++) {
        int id = tid + 128*i;
        int r  = id >> 3;
        cp16(&QS(r, kc), &Qp[(size_t)(qb + r)*NDH + kc]);
    }
    A_FILL(0, 0);
    cp_wait<0>();
    __syncthreads();

    unsigned qf[2][4][4];
#pragma unroll
    for (int mt = 0; mt < 2; mt++)
#pragma unroll
        for (int kt = 0; kt < 4; kt++)
            ldsm_x4(qf[mt][kt], &QS(warp*32 + mt*16 + (lane & 15), kt*16 + (lane >> 4)*8));

    float o[2][9][4];
#pragma unroll
    for (int mt = 0; mt < 2; mt++)
#pragma unroll
        for (int nt = 0; nt < 9; nt++)
#pragma unroll
            for (int e = 0; e < 4; e++) o[mt][nt][e] = 0.f;

    const unsigned ones_frag[2] = { ONES_H2, ONES_H2 };

    const int ntiles = NT >> 6;

    for (int it = 0; it < ntiles; it++) {
        const int buf = it & 1;
        if (it + 1 < ntiles) A_FILL(buf^1, (it + 1) << 6);

        // S = Q K^T   (kt=0 init-form MMA)
        float sv[2][8][4];
        {
            unsigned kf[8][2];
#pragma unroll
            for (int nt2 = 0; nt2 < 4; nt2++) {
                unsigned kq[4];
                ldsm_x4(kq, &KS(buf, nt2*16 + (lane >> 4)*8 + (lane & 7),
                                     ((lane >> 3) & 1)*8));
                kf[2*nt2  ][0] = kq[0]; kf[2*nt2  ][1] = kq[1];
                kf[2*nt2+1][0] = kq[2]; kf[2*nt2+1][1] = kq[3];
            }
#pragma unroll
            for (int mt = 0; mt < 2; mt++)
#pragma unroll
                for (int nt = 0; nt < 8; nt++)
                    mma_16816_z(sv[mt][nt], qf[mt][0], kf[nt]);
        }
#pragma unroll
        for (int kt = 1; kt < 4; kt++) {
            unsigned kf[8][2];
#pragma unroll
            for (int nt2 = 0; nt2 < 4; nt2++) {
                unsigned kq[4];
                ldsm_x4(kq, &KS(buf, nt2*16 + (lane >> 4)*8 + (lane & 7),
                                     kt*16 + ((lane >> 3) & 1)*8));
                kf[2*nt2  ][0] = kq[0]; kf[2*nt2  ][1] = kq[1];
                kf[2*nt2+1][0] = kq[2]; kf[2*nt2+1][1] = kq[3];
            }
#pragma unroll
            for (int mt = 0; mt < 2; mt++)
#pragma unroll
                for (int nt = 0; nt < 8; nt++)
                    mma_16816(sv[mt][nt], qf[mt][kt], kf[nt]);
        }

        // p = 2^s (f16x2) -> PV A-fragment
        unsigned pf[2][4][4];
#pragma unroll
        for (int mt = 0; mt < 2; mt++)
#pragma unroll
            for (int kt = 0; kt < 4; kt++) {
                pf[mt][kt][0] = h2ex2(packh2(sv[mt][2*kt  ][0], sv[mt][2*kt  ][1]));
                pf[mt][kt][1] = h2ex2(packh2(sv[mt][2*kt  ][2], sv[mt][2*kt  ][3]));
                pf[mt][kt][2] = h2ex2(packh2(sv[mt][2*kt+1][0], sv[mt][2*kt+1][1]));
                pf[mt][kt][3] = h2ex2(packh2(sv[mt][2*kt+1][2], sv[mt][2*kt+1][3]));
            }

        // O += P V  (nt=8 uses the constant ones fragment -> denominator)
#pragma unroll
        for (int kt = 0; kt < 4; kt++) {
            unsigned vf[8][2];
#pragma unroll
            for (int nt2 = 0; nt2 < 4; nt2++) {
                unsigned vq[4];
                ldsm_x4t(vq, &VS(buf, kt*16 + (lane & 15), nt2*16 + (lane >> 4)*8));
                vf[2*nt2  ][0] = vq[0]; vf[2*nt2  ][1] = vq[1];
                vf[2*nt2+1][0] = vq[2]; vf[2*nt2+1][1] = vq[3];
            }
#pragma unroll
            for (int mt = 0; mt < 2; mt++) {
#pragma unroll
                for (int nt = 0; nt < 8; nt++)
                    mma_16816(o[mt][nt], pf[mt][kt], vf[nt]);
                mma_16816(o[mt][8], pf[mt][kt], ones_frag);
            }
        }

        if (it + 1 < ntiles) {
            cp_wait<0>();
            __syncthreads();
        }
    }

    const int b = bh >> 4;
    const int h = bh & 15;
#pragma unroll
    for (int mt = 0; mt < 2; mt++) {
#pragma unroll
        for (int hr = 0; hr < 2; hr++) {
            float inv = 1.0f / o[mt][8][hr*2];
            int row = qb + warp*32 + mt*16 + (lane >> 2) + hr*8;
            size_t rowoff = ((size_t)b*NT + row)*NDIM + h*NDH;
#pragma unroll
            for (int nt = 0; nt < 8; nt++) {
                int col = nt*8 + (lane & 3)*2;
                *reinterpret_cast<__half2*>(&g_O[rowoff + col]) =
                    __floats2half2_rn(o[mt][nt][hr*2+0]*inv, o[mt][nt][hr*2+1]*inv);
            }
        }
    }
#undef QS
#undef KS
#undef VS
#undef A_FILL
}

// ---------------- launch ----------------
extern "C" void kernel_launch(void* const* d_in, const int* in_sizes, int n_in,
                              void* d_out, int out_size) {
    (void)in_sizes; (void)n_in; (void)out_size;
    const float* x    = (const float*)d_in[0];
    const float* Wqkv = (const float*)d_in[1];
    const float* Wo   = (const float*)d_in[2];
    float* out = (float*)d_out;

    static bool attr_done = false;
    if (!attr_done) {
        cudaFuncSetAttribute(gemm_kernel<0>, cudaFuncAttributeMaxDynamicSharedMemorySize, GEMM_SMEM_BYTES);
        cudaFuncSetAttribute(gemm_kernel<1>, cudaFuncAttributeMaxDynamicSharedMemorySize, GEMM_SMEM_BYTES);
        cudaFuncSetAttribute(attn_kernel,    cudaFuncAttributeMaxDynamicSharedMemorySize, ATTN_SMEM_BYTES);
        attr_done = true;
    }

    __half *xh_p, *wqkv_p, *wo_p, *o_p;
    cudaGetSymbolAddress((void**)&xh_p,   g_xh);
    cudaGetSymbolAddress((void**)&wqkv_p, g_Wqkv);
    cudaGetSymbolAddress((void**)&wo_p,   g_Wo);
    cudaGetSymbolAddress((void**)&o_p,    g_O);

    // conversions: coalesced x/Wo convert + smem-staged Wqkv permute
    cvt_xw_kernel<<<2048, 256>>>(x, Wo);
    permw_kernel<<<NDIM, 256>>>(Wqkv);

    {
        dim3 grid(3*NDIM/128, NB*NT/128);   // (24, 64)
        gemm_kernel<0><<<grid, 256, GEMM_SMEM_BYTES>>>(xh_p, wqkv_p, NDIM, 3*NDIM, nullptr);
    }
    {
        dim3 grid(NT/128, BHN);             // (16, 64)
        attn_kernel<<<grid, 128, ATTN_SMEM_BYTES>>>();
    }
    {
        dim3 grid(NDIM/128, NB*NT/128);     // (8, 64)
        gemm_kernel<1><<<grid, 256, GEMM_SMEM_BYTES>>>(o_p, wo_p, NDIM, NDIM, out);
    }
}

// round 16
// speedup vs baseline: 1.0769x; 1.0344x over previous
#include <cuda_runtime.h>
#include <cuda_fp16.h>
#include <cstdint>

#define NB 4
#define NT 2048
#define NDIM 1024
#define NH 16
#define NDH 64
#define BHN (NB*NH)

// softmax scale folded into Q: 0.125 * log2(e)
#define C2F 0.18033688011112042f
// fp16x2 {1.0, 1.0}
#define ONES_H2 0x3C003C00u

// ---------------- scratch ----------------
__device__ __half g_xh[NB*NT*NDIM];
__device__ __half g_Wqkv[NDIM*3*NDIM];   // [k=1024][n=3072], permuted cols
__device__ __half g_Wo[NDIM*NDIM];       // [k=1024][n=1024]
__device__ __half g_Q[BHN*NT*NDH];       // pre-scaled by C2F
__device__ __half g_K[BHN*NT*NDH];
__device__ __half g_V[BHN*NT*NDH];
__device__ __half g_O[NB*NT*NDIM];

// ---------------- helpers ----------------
__device__ __forceinline__ unsigned smem_u32(const void* p) {
    return (unsigned)__cvta_generic_to_shared(p);
}
__device__ __forceinline__ void cp16(void* s, const void* g) {
    asm volatile("cp.async.cg.shared.global [%0], [%1], 16;\n"
                 :: "r"(smem_u32(s)), "l"(g));
}
__device__ __forceinline__ void cp_commit() { asm volatile("cp.async.commit_group;\n"); }
template <int N>
__device__ __forceinline__ void cp_wait() { asm volatile("cp.async.wait_group %0;\n" :: "n"(N)); }

__device__ __forceinline__ void ldsm_x4(unsigned r[4], const void* p) {
    unsigned a = smem_u32(p);
    asm volatile("ldmatrix.sync.aligned.m8n8.x4.shared.b16 {%0,%1,%2,%3}, [%4];\n"
                 : "=r"(r[0]), "=r"(r[1]), "=r"(r[2]), "=r"(r[3]) : "r"(a));
}
__device__ __forceinline__ void ldsm_x4t(unsigned r[4], const void* p) {
    unsigned a = smem_u32(p);
    asm volatile("ldmatrix.sync.aligned.m8n8.x4.trans.shared.b16 {%0,%1,%2,%3}, [%4];\n"
                 : "=r"(r[0]), "=r"(r[1]), "=r"(r[2]), "=r"(r[3]) : "r"(a));
}
__device__ __forceinline__ void mma_16816(float c[4], const unsigned a[4], const unsigned b[2]) {
    asm volatile(
        "mma.sync.aligned.m16n8k16.row.col.f32.f16.f16.f32 "
        "{%0,%1,%2,%3}, {%4,%5,%6,%7}, {%8,%9}, {%0,%1,%2,%3};\n"
        : "+f"(c[0]), "+f"(c[1]), "+f"(c[2]), "+f"(c[3])
        : "r"(a[0]), "r"(a[1]), "r"(a[2]), "r"(a[3]), "r"(b[0]), "r"(b[1]));
}
// init form: D = A*B + 0
__device__ __forceinline__ void mma_16816_z(float d[4], const unsigned a[4], const unsigned b[2]) {
    asm volatile(
        "mma.sync.aligned.m16n8k16.row.col.f32.f16.f16.f32 "
        "{%0,%1,%2,%3}, {%4,%5,%6,%7}, {%8,%9}, {%10,%11,%12,%13};\n"
        : "=f"(d[0]), "=f"(d[1]), "=f"(d[2]), "=f"(d[3])
        : "r"(a[0]), "r"(a[1]), "r"(a[2]), "r"(a[3]), "r"(b[0]), "r"(b[1]),
          "f"(0.f), "f"(0.f), "f"(0.f), "f"(0.f));
}
__device__ __forceinline__ unsigned packh2(float lo, float hi) {
    __half2 h = __floats2half2_rn(lo, hi);
    return *reinterpret_cast<unsigned*>(&h);
}
__device__ __forceinline__ unsigned h2ex2(unsigned x) {
    unsigned y;
    asm("ex2.approx.f16x2 %0, %1;" : "=r"(y) : "r"(x));
    return y;
}

// ---------------- fused conversion kernel (R12 proven) ----------------
#define NX4 ((NB*NT*NDIM)/4)
#define NPW (NDIM*3*NDIM)
#define NW4 ((NDIM*NDIM)/4)
__global__ void cvt_all_kernel(const float* __restrict__ x,
                               const float* __restrict__ Wqkv,
                               const float* __restrict__ Wo) {
    int i = blockIdx.x * blockDim.x + threadIdx.x;
    int total = NX4 + NPW + NW4;
    for (; i < total; i += gridDim.x * blockDim.x) {
        if (i < NX4) {
            float4 v = reinterpret_cast<const float4*>(x)[i];
            __half2* dst = reinterpret_cast<__half2*>(g_xh) + i*2;
            dst[0] = __floats2half2_rn(v.x, v.y);
            dst[1] = __floats2half2_rn(v.z, v.w);
        } else if (i < NX4 + NPW) {
            int j = i - NX4;
            int k   = j / (3*NDIM);
            int nn  = j - k * (3*NDIM);
            int kqv = nn >> 10;
            int rem = nn & 1023;
            int h   = rem >> 6;
            int d   = rem & 63;
            g_Wqkv[j] = __float2half_rn(Wqkv[k*(3*NDIM) + d*48 + kqv*16 + h]);
        } else {
            int j = i - NX4 - NPW;
            float4 v = reinterpret_cast<const float4*>(Wo)[j];
            __half2* dst = reinterpret_cast<__half2*>(g_Wo) + j*2;
            dst[0] = __floats2half2_rn(v.x, v.y);
            dst[1] = __floats2half2_rn(v.z, v.w);
        }
    }
}

// ---------------- pipelined GEMM (R12 proven: 8 warps, 64x32 warp tile) ----------------
#define GEMM_SMEM_BYTES ((2*128*72 + 2*64*136) * 2)

__device__ __forceinline__ void store_qkv(int row, int col, float v0, float v1) {
    int kqv = col >> 10;
    int rem = col & 1023;
    int h   = rem >> 6;
    int d   = rem & 63;
    int b   = row >> 11;
    int t   = row & 2047;
    float sc = (kqv == 0) ? C2F : 1.0f;
    __half* base = (kqv == 0) ? g_Q : ((kqv == 1) ? g_K : g_V);
    *reinterpret_cast<__half2*>(&base[(((size_t)(b*NH + h))*NT + t)*NDH + d]) =
        __floats2half2_rn(v0*sc, v1*sc);
}

template <int MODE>
__global__ __launch_bounds__(256, 2) void gemm_kernel(
    const __half* __restrict__ A, const __half* __restrict__ Bm,
    int K, int ldb, float* __restrict__ outF)
{
    extern __shared__ __half dyn[];
    __half* As0 = dyn;                 // [2][128][72]
    __half* Bs0 = dyn + 2*128*72;      // [2][64][136]
#define AS(bf,r,c) As0[((bf)*128 + (r))*72 + (c)]
#define BS(bf,r,c) Bs0[((bf)*64  + (r))*136 + (c)]

    const int tid  = threadIdx.x;
    const int lane = tid & 31;
    const int warp = tid >> 5;
    const int wm   = warp & 1;
    const int wn   = warp >> 1;
    const int m0   = blockIdx.y * 128;
    const int n0   = blockIdx.x * 128;

    const int ar[4] = { (tid+0)>>3, (tid+256)>>3, (tid+512)>>3, (tid+768)>>3 };
    const int ac    = (tid & 7) * 8;
    const int br[4] = { (tid+0)>>4, (tid+256)>>4, (tid+512)>>4, (tid+768)>>4 };
    const int bc    = (tid & 15) * 8;

    float acc[4][4][4];
#pragma unroll
    for (int mt = 0; mt < 4; mt++)
#pragma unroll
        for (int nt = 0; nt < 4; nt++)
#pragma unroll
            for (int e = 0; e < 4; e++) acc[mt][nt][e] = 0.f;

    const int ntiles = K >> 6;

#define G_FILL(bf, kb) do {                                                    \
        _Pragma("unroll")                                                      \
        for (int i_ = 0; i_ < 4; i_++)                                         \
            cp16(&AS(bf, ar[i_], ac), &A[(size_t)(m0 + ar[i_])*K + (kb) + ac]);\
        _Pragma("unroll")                                                      \
        for (int i_ = 0; i_ < 4; i_++)                                         \
            cp16(&BS(bf, br[i_], bc), &Bm[(size_t)((kb) + br[i_])*ldb + n0 + bc]); \
        cp_commit();                                                           \
    } while (0)

    G_FILL(0, 0);

    for (int it = 0; it < ntiles; it++) {
        const int buf = it & 1;
        cp_wait<0>();
        __syncthreads();
        if (it + 1 < ntiles) G_FILL(buf^1, (it + 1) << 6);

#pragma unroll
        for (int kk = 0; kk < 4; kk++) {
            unsigned af[4][4], bfr[4][2];
#pragma unroll
            for (int mt = 0; mt < 4; mt++)
                ldsm_x4(af[mt], &AS(buf, wm*64 + mt*16 + (lane & 15), kk*16 + (lane >> 4)*8));
#pragma unroll
            for (int nt2 = 0; nt2 < 2; nt2++) {
                unsigned bq[4];
                ldsm_x4t(bq, &BS(buf, kk*16 + (lane & 15), wn*32 + nt2*16 + (lane >> 4)*8));
                bfr[2*nt2  ][0] = bq[0]; bfr[2*nt2  ][1] = bq[1];
                bfr[2*nt2+1][0] = bq[2]; bfr[2*nt2+1][1] = bq[3];
            }
#pragma unroll
            for (int mt = 0; mt < 4; mt++)
#pragma unroll
                for (int nt = 0; nt < 4; nt++)
                    mma_16816(acc[mt][nt], af[mt], bfr[nt]);
        }
    }

#pragma unroll
    for (int mt = 0; mt < 4; mt++) {
        int row = m0 + wm*64 + mt*16 + (lane >> 2);
#pragma unroll
        for (int nt = 0; nt < 4; nt++) {
            int col = n0 + wn*32 + nt*8 + (lane & 3)*2;
            if (MODE == 0) {
                store_qkv(row,     col, acc[mt][nt][0], acc[mt][nt][1]);
                store_qkv(row + 8, col, acc[mt][nt][2], acc[mt][nt][3]);
            } else {
                *reinterpret_cast<float2*>(&outF[(size_t)row*NDIM + col]) =
                    make_float2(acc[mt][nt][0], acc[mt][nt][1]);
                *reinterpret_cast<float2*>(&outF[(size_t)(row+8)*NDIM + col]) =
                    make_float2(acc[mt][nt][2], acc[mt][nt][3]);
            }
        }
    }
#undef AS
#undef BS
#undef G_FILL
}

// ---------------- flash attention (R12 config, 3 CTAs/SM register cap) ----------------
#define ATTN_SMEM_BYTES ((128*72 + 2*64*72 + 2*64*72) * 2)

__global__ __launch_bounds__(128, 3) void attn_kernel() {
    extern __shared__ __half dynA[];
    __half* Qs0 = dynA;
    __half* Ks0 = dynA + 128*72;
    __half* Vs0 = dynA + 128*72 + 2*64*72;
#define QS(r,c)    Qs0[(r)*72 + (c)]
#define KS(bf,r,c) Ks0[((bf)*64 + (r))*72 + (c)]
#define VS(bf,r,c) Vs0[((bf)*64 + (r))*72 + (c)]

    const int tid  = threadIdx.x;
    const int lane = tid & 31;
    const int warp = tid >> 5;
    const int qb   = blockIdx.x * 128;
    const int bh   = blockIdx.y;

    const __half* Qp = g_Q + (size_t)bh * NT * NDH;
    const __half* Kp = g_K + (size_t)bh * NT * NDH;
    const __half* Vp = g_V + (size_t)bh * NT * NDH;

    const int kr[4] = { (tid+0)>>3, (tid+128)>>3, (tid+256)>>3, (tid+384)>>3 };
    const int kc    = (tid & 7) * 8;

#define A_FILL(bf, jb) do {                                                    \
        _Pragma("unroll")                                                      \
        for (int i_ = 0; i_ < 4; i_++) {                                       \
            cp16(&KS(bf, kr[i_], kc), &Kp[(size_t)((jb) + kr[i_])*NDH + kc]);  \
            cp16(&VS(bf, kr[i_], kc), &Vp[(size_t)((jb) + kr[i_])*NDH + kc]);  \
        }                                                                      \
        cp_commit();                                                           \
    } while (0)

    // prologue: Q + KV tile 0
#pragma unroll
    for (int i = 0; i < 8; i++) {
        int id = tid + 128*i;
        int r  = id >> 3;
        cp16(&QS(r, kc), &Qp[(size_t)(qb + r)*NDH + kc]);
    }
    A_FILL(0, 0);
    cp_wait<0>();
    __syncthreads();

    unsigned qf[2][4][4];
#pragma unroll
    for (int mt = 0; mt < 2; mt++)
#pragma unroll
        for (int kt = 0; kt < 4; kt++)
            ldsm_x4(qf[mt][kt], &QS(warp*32 + mt*16 + (lane & 15), kt*16 + (lane >> 4)*8));

    float o[2][9][4];
#pragma unroll
    for (int mt = 0; mt < 2; mt++)
#pragma unroll
        for (int nt = 0; nt < 9; nt++)
#pragma unroll
            for (int e = 0; e < 4; e++) o[mt][nt][e] = 0.f;

    const unsigned ones_frag[2] = { ONES_H2, ONES_H2 };

    const int ntiles = NT >> 6;

    for (int it = 0; it < ntiles; it++) {
        const int buf = it & 1;
        if (it + 1 < ntiles) A_FILL(buf^1, (it + 1) << 6);

        // S = Q K^T   (kt=0 init-form MMA)
        float sv[2][8][4];
        {
            unsigned kf[8][2];
#pragma unroll
            for (int nt2 = 0; nt2 < 4; nt2++) {
                unsigned kq[4];
                ldsm_x4(kq, &KS(buf, nt2*16 + (lane >> 4)*8 + (lane & 7),
                                     ((lane >> 3) & 1)*8));
                kf[2*nt2  ][0] = kq[0]; kf[2*nt2  ][1] = kq[1];
                kf[2*nt2+1][0] = kq[2]; kf[2*nt2+1][1] = kq[3];
            }
#pragma unroll
            for (int mt = 0; mt < 2; mt++)
#pragma unroll
                for (int nt = 0; nt < 8; nt++)
                    mma_16816_z(sv[mt][nt], qf[mt][0], kf[nt]);
        }
#pragma unroll
        for (int kt = 1; kt < 4; kt++) {
            unsigned kf[8][2];
#pragma unroll
            for (int nt2 = 0; nt2 < 4; nt2++) {
                unsigned kq[4];
                ldsm_x4(kq, &KS(buf, nt2*16 + (lane >> 4)*8 + (lane & 7),
                                     kt*16 + ((lane >> 3) & 1)*8));
                kf[2*nt2  ][0] = kq[0]; kf[2*nt2  ][1] = kq[1];
                kf[2*nt2+1][0] = kq[2]; kf[2*nt2+1][1] = kq[3];
            }
#pragma unroll
            for (int mt = 0; mt < 2; mt++)
#pragma unroll
                for (int nt = 0; nt < 8; nt++)
                    mma_16816(sv[mt][nt], qf[mt][kt], kf[nt]);
        }

        // p = 2^s (f16x2) -> PV A-fragment
        unsigned pf[2][4][4];
#pragma unroll
        for (int mt = 0; mt < 2; mt++)
#pragma unroll
            for (int kt = 0; kt < 4; kt++) {
                pf[mt][kt][0] = h2ex2(packh2(sv[mt][2*kt  ][0], sv[mt][2*kt  ][1]));
                pf[mt][kt][1] = h2ex2(packh2(sv[mt][2*kt  ][2], sv[mt][2*kt  ][3]));
                pf[mt][kt][2] = h2ex2(packh2(sv[mt][2*kt+1][0], sv[mt][2*kt+1][1]));
                pf[mt][kt][3] = h2ex2(packh2(sv[mt][2*kt+1][2], sv[mt][2*kt+1][3]));
            }

        // O += P V  (nt=8 uses the constant ones fragment -> denominator)
#pragma unroll
        for (int kt = 0; kt < 4; kt++) {
            unsigned vf[8][2];
#pragma unroll
            for (int nt2 = 0; nt2 < 4; nt2++) {
                unsigned vq[4];
                ldsm_x4t(vq, &VS(buf, kt*16 + (lane & 15), nt2*16 + (lane >> 4)*8));
                vf[2*nt2  ][0] = vq[0]; vf[2*nt2  ][1] = vq[1];
                vf[2*nt2+1][0] = vq[2]; vf[2*nt2+1][1] = vq[3];
            }
#pragma unroll
            for (int mt = 0; mt < 2; mt++) {
#pragma unroll
                for (int nt = 0; nt < 8; nt++)
                    mma_16816(o[mt][nt], pf[mt][kt], vf[nt]);
                mma_16816(o[mt][8], pf[mt][kt], ones_frag);
            }
        }

        if (it + 1 < ntiles) {
            cp_wait<0>();
            __syncthreads();
        }
    }

    const int b = bh >> 4;
    const int h = bh & 15;
#pragma unroll
    for (int mt = 0; mt < 2; mt++) {
#pragma unroll
        for (int hr = 0; hr < 2; hr++) {
            float inv = 1.0f / o[mt][8][hr*2];
            int row = qb + warp*32 + mt*16 + (lane >> 2) + hr*8;
            size_t rowoff = ((size_t)b*NT + row)*NDIM + h*NDH;
#pragma unroll
            for (int nt = 0; nt < 8; nt++) {
                int col = nt*8 + (lane & 3)*2;
                *reinterpret_cast<__half2*>(&g_O[rowoff + col]) =
                    __floats2half2_rn(o[mt][nt][hr*2+0]*inv, o[mt][nt][hr*2+1]*inv);
            }
        }
    }
#undef QS
#undef KS
#undef VS
#undef A_FILL
}

// ---------------- launch ----------------
extern "C" void kernel_launch(void* const* d_in, const int* in_sizes, int n_in,
                              void* d_out, int out_size) {
    (void)in_sizes; (void)n_in; (void)out_size;
    const float* x    = (const float*)d_in[0];
    const float* Wqkv = (const float*)d_in[1];
    const float* Wo   = (const float*)d_in[2];
    float* out = (float*)d_out;

    static bool attr_done = false;
    if (!attr_done) {
        cudaFuncSetAttribute(gemm_kernel<0>, cudaFuncAttributeMaxDynamicSharedMemorySize, GEMM_SMEM_BYTES);
        cudaFuncSetAttribute(gemm_kernel<1>, cudaFuncAttributeMaxDynamicSharedMemorySize, GEMM_SMEM_BYTES);
        cudaFuncSetAttribute(attn_kernel,    cudaFuncAttributeMaxDynamicSharedMemorySize, ATTN_SMEM_BYTES);
        attr_done = true;
    }

    __half *xh_p, *wqkv_p, *wo_p, *o_p;
    cudaGetSymbolAddress((void**)&xh_p,   g_xh);
    cudaGetSymbolAddress((void**)&wqkv_p, g_Wqkv);
    cudaGetSymbolAddress((void**)&wo_p,   g_Wo);
    cudaGetSymbolAddress((void**)&o_p,    g_O);

    cvt_all_kernel<<<4096, 256>>>(x, Wqkv, Wo);

    {
        dim3 grid(3*NDIM/128, NB*NT/128);   // (24, 64)
        gemm_kernel<0><<<grid, 256, GEMM_SMEM_BYTES>>>(xh_p, wqkv_p, NDIM, 3*NDIM, nullptr);
    }
    {
        dim3 grid(NT/128, BHN);             // (16, 64)
        attn_kernel<<<grid, 128, ATTN_SMEM_BYTES>>>();
    }
    {
        dim3 grid(NDIM/128, NB*NT/128);     // (8, 64)
        gemm_kernel<1><<<grid, 256, GEMM_SMEM_BYTES>>>(o_p, wo_p, NDIM, NDIM, out);
    }
}